// round 1
// baseline (speedup 1.0000x reference)
#include <cuda_runtime.h>
#include <math.h>

#define N_NODES 100000
#define N_EDGES 3200000
#define F_IN    512
#define HID     128
#define N_CLS   16

// ---------------- scratch (static device globals; no allocation) ----------
__device__ int   g_cnt[N_NODES];           // edge count per row
__device__ int   g_off[N_NODES];           // CSR row offsets (exclusive scan of cnt)
__device__ int   g_cur[N_NODES];           // fill cursors
__device__ float g_dinv[N_NODES];          // deg^{-1/2}
__device__ int   g_ccol[N_EDGES];          // CSR column indices
__device__ float g_cnorm[N_EDGES];         // per-edge norm = dinv[r]*dinv[c]
__device__ float g_bufA[(size_t)N_NODES * HID];
__device__ float g_bufB[(size_t)N_NODES * HID];

// ---------------- CSR construction ----------------------------------------
__global__ void zero_kernel(int n) {
    int i = blockIdx.x * blockDim.x + threadIdx.x;
    if (i < n) { g_cnt[i] = 0; g_cur[i] = 0; }
}

__global__ void count_kernel(const int* __restrict__ rows, int E) {
    int e = blockIdx.x * blockDim.x + threadIdx.x;
    if (e < E) atomicAdd(&g_cnt[rows[e]], 1);
}

__global__ void dinv_kernel(int n, float fill) {
    int i = blockIdx.x * blockDim.x + threadIdx.x;
    if (i < n) g_dinv[i] = rsqrtf((float)g_cnt[i] + fill);
}

// one-block scan: 1024 threads, each handles a contiguous segment
__global__ void scan_kernel(int n) {
    __shared__ int ssum[1024];
    int t = threadIdx.x;
    int seg = (n + 1023) >> 10;
    int s0 = t * seg;
    int s1 = min(s0 + seg, n);
    int sum = 0;
    for (int i = s0; i < s1; i++) sum += g_cnt[i];
    ssum[t] = sum;
    __syncthreads();
    // Hillis-Steele inclusive scan over 1024
    for (int d = 1; d < 1024; d <<= 1) {
        int v = (t >= d) ? ssum[t - d] : 0;
        __syncthreads();
        ssum[t] += v;
        __syncthreads();
    }
    int run = (t == 0) ? 0 : ssum[t - 1];
    for (int i = s0; i < s1; i++) { g_off[i] = run; run += g_cnt[i]; }
}

__global__ void fill_kernel(const int* __restrict__ rows,
                            const int* __restrict__ cols, int E) {
    int e = blockIdx.x * blockDim.x + threadIdx.x;
    if (e < E) {
        int r = rows[e];
        int c = cols[e];
        int p = g_off[r] + atomicAdd(&g_cur[r], 1);
        g_ccol[p]  = c;
        g_cnorm[p] = g_dinv[r] * g_dinv[c];
    }
}

// ---------------- fp32 tiled GEMM: C[M x 128] = A[M x K] @ B[K x 128] ------
// 64-row blocks, 256 threads, thread computes 8 rows x 4 cols, KC=16 chunks.
#define KC 16
__global__ void gemm128_kernel(const float* __restrict__ A,
                               const float* __restrict__ B,
                               float* __restrict__ C, int M, int K) {
    __shared__ float As[KC][64];    // [k][m]
    __shared__ float Bs[KC][128];   // [k][n]
    int tid = threadIdx.x;
    int m0  = blockIdx.x * 64;
    int ty  = tid >> 5;             // 0..7 row-group
    int tx  = tid & 31;             // col-group (4 cols each)

    float acc[8][4];
#pragma unroll
    for (int r = 0; r < 8; r++)
#pragma unroll
        for (int j = 0; j < 4; j++) acc[r][j] = 0.f;

    for (int k0 = 0; k0 < K; k0 += KC) {
        // A tile: 64 x 16 -> each thread one float4 along k
        {
            int r  = tid >> 2;
            int kq = (tid & 3) * 4;
            int gm = m0 + r;
            float4 a = make_float4(0.f, 0.f, 0.f, 0.f);
            if (gm < M) a = *(const float4*)&A[(size_t)gm * K + k0 + kq];
            As[kq + 0][r] = a.x;
            As[kq + 1][r] = a.y;
            As[kq + 2][r] = a.z;
            As[kq + 3][r] = a.w;
        }
        // B tile: 16 x 128 -> 2 float4 per thread
#pragma unroll
        for (int i = 0; i < 2; i++) {
            int idx = tid + i * 256;      // float4 index over [KC][32]
            int kk  = idx >> 5;
            int c4  = idx & 31;
            float4 b = *(const float4*)&B[(size_t)(k0 + kk) * 128 + c4 * 4];
            *(float4*)&Bs[kk][c4 * 4] = b;
        }
        __syncthreads();
#pragma unroll
        for (int k = 0; k < KC; k++) {
            float a[8];
#pragma unroll
            for (int r = 0; r < 8; r++) a[r] = As[k][ty * 8 + r];
            float4 b = *(const float4*)&Bs[k][tx * 4];
#pragma unroll
            for (int r = 0; r < 8; r++) {
                acc[r][0] += a[r] * b.x;
                acc[r][1] += a[r] * b.y;
                acc[r][2] += a[r] * b.z;
                acc[r][3] += a[r] * b.w;
            }
        }
        __syncthreads();
    }
#pragma unroll
    for (int r = 0; r < 8; r++) {
        int gm = m0 + ty * 8 + r;
        if (gm < M) {
            float4 o = make_float4(acc[r][0], acc[r][1], acc[r][2], acc[r][3]);
            *(float4*)&C[(size_t)gm * 128 + tx * 4] = o;
        }
    }
}

// ---------------- aggregation: out[r] = sum_e norm_e * h[col_e] + self ----
template <bool RELU>
__global__ void agg_kernel(const float* __restrict__ h,
                           float* __restrict__ out, int n, float fill) {
    int warp = (blockIdx.x * blockDim.x + threadIdx.x) >> 5;
    int lane = threadIdx.x & 31;
    if (warp >= n) return;
    const float4* hv = (const float4*)h;

    float di = g_dinv[warp];
    float ws = fill * di * di;             // self-loop weight
    float4 v = hv[(size_t)warp * 32 + lane];
    float4 acc = make_float4(ws * v.x, ws * v.y, ws * v.z, ws * v.w);

    int s = g_off[warp];
    int c = g_cnt[warp];
    for (int j = 0; j < c; j++) {
        int   col = __ldg(&g_ccol[s + j]);
        float w   = __ldg(&g_cnorm[s + j]);
        float4 u  = hv[(size_t)col * 32 + lane];
        acc.x += w * u.x;
        acc.y += w * u.y;
        acc.z += w * u.z;
        acc.w += w * u.w;
    }
    if (RELU) {
        acc.x = fmaxf(acc.x, 0.f);
        acc.y = fmaxf(acc.y, 0.f);
        acc.z = fmaxf(acc.z, 0.f);
        acc.w = fmaxf(acc.w, 0.f);
    }
    *(float4*)&out[(size_t)warp * 128 + lane * 4] = acc;
}

// ---------------- classifier: out[n,c] = h[n,:] . W3[c,:] + b3[c] ----------
__global__ void cls_kernel(const float* __restrict__ h,
                           const float* __restrict__ W3,
                           const float* __restrict__ b3,
                           float* __restrict__ out, int n) {
    __shared__ float sW[N_CLS * HID];
    __shared__ float sb[N_CLS];
    for (int i = threadIdx.x; i < N_CLS * HID; i += blockDim.x) sW[i] = W3[i];
    if (threadIdx.x < N_CLS) sb[threadIdx.x] = b3[threadIdx.x];
    __syncthreads();

    int warp = (blockIdx.x * blockDim.x + threadIdx.x) >> 5;
    int lane = threadIdx.x & 31;
    if (warp >= n) return;

    float4 v = *(const float4*)&h[(size_t)warp * 128 + lane * 4];
#pragma unroll
    for (int c = 0; c < N_CLS; c++) {
        float4 w = *(const float4*)&sW[c * 128 + lane * 4];
        float  p = v.x * w.x + v.y * w.y + v.z * w.z + v.w * w.w;
        p += __shfl_xor_sync(0xffffffffu, p, 16);
        p += __shfl_xor_sync(0xffffffffu, p, 8);
        p += __shfl_xor_sync(0xffffffffu, p, 4);
        p += __shfl_xor_sync(0xffffffffu, p, 2);
        p += __shfl_xor_sync(0xffffffffu, p, 1);
        if (lane == 0) out[(size_t)warp * N_CLS + c] = p + sb[c];
    }
}

// ---------------- launch ---------------------------------------------------
extern "C" void kernel_launch(void* const* d_in, const int* in_sizes, int n_in,
                              void* d_out, int out_size) {
    const float* x  = (const float*)d_in[0];
    const int*   ei = (const int*)d_in[1];
    const float* W1 = (const float*)d_in[2];
    const float* W2 = (const float*)d_in[3];
    const float* W3 = (const float*)d_in[4];
    const float* b3 = (const float*)d_in[5];
    float* out = (float*)d_out;

    const int E = in_sizes[1] / 2;
    const int N = in_sizes[0] / F_IN;
    const int* rows = ei;
    const int* cols = ei + E;
    const float fill = truncf(log2f((float)E / (float)N));

    float* bufA;  cudaGetSymbolAddress((void**)&bufA, g_bufA);
    float* bufB;  cudaGetSymbolAddress((void**)&bufB, g_bufB);

    const int T = 256;
    // --- CSR build ---
    zero_kernel<<<(N + T - 1) / T, T>>>(N);
    count_kernel<<<(E + T - 1) / T, T>>>(rows, E);
    dinv_kernel<<<(N + T - 1) / T, T>>>(N, fill);
    scan_kernel<<<1, 1024>>>(N);
    fill_kernel<<<(E + T - 1) / T, T>>>(rows, cols, E);

    // --- layer 1: X @ W1 -> aggregate -> ReLU ---
    gemm128_kernel<<<(N + 63) / 64, 256>>>(x, W1, bufA, N, F_IN);
    agg_kernel<true><<<(N * 32 + T - 1) / T, T>>>(bufA, bufB, N, fill);

    // --- layer 2: H1 @ W2 -> aggregate ---
    gemm128_kernel<<<(N + 63) / 64, 256>>>(bufB, W2, bufA, N, HID);
    agg_kernel<false><<<(N * 32 + T - 1) / T, T>>>(bufA, bufB, N, fill);

    // --- classifier ---
    cls_kernel<<<(N * 32 + T - 1) / T, T>>>(bufB, W3, b3, out, N);
}

// round 2
// speedup vs baseline: 1.1905x; 1.1905x over previous
#include <cuda_runtime.h>
#include <math.h>

#define N_NODES 100000
#define N_EDGES 3200000
#define F_IN    512
#define HID     128
#define N_CLS   16

// ---------------- scratch (static device globals; no allocation) ----------
__device__ int   g_cnt[N_NODES];
__device__ int   g_off[N_NODES];
__device__ int   g_cur[N_NODES];
__device__ float g_dinv[N_NODES];
__device__ int   g_total;
__device__ int   g_ccol[N_EDGES];
__device__ float g_cnorm[N_EDGES];
__device__ float g_bufA[(size_t)N_NODES * HID];
__device__ float g_bufB[(size_t)N_NODES * HID];

// ---------------- CSR construction ----------------------------------------
__global__ void zero_kernel(int n) {
    int i = blockIdx.x * blockDim.x + threadIdx.x;
    if (i < n) { g_cnt[i] = 0; g_cur[i] = 0; }
    if (i == 0) g_total = 0;
}

__global__ void count_kernel(const int* __restrict__ rows, int E) {
    int e = blockIdx.x * blockDim.x + threadIdx.x;
    if (e < E) atomicAdd(&g_cnt[rows[e]], 1);
}

__global__ void dinv_kernel(int n, float fill) {
    int i = blockIdx.x * blockDim.x + threadIdx.x;
    if (i < n) g_dinv[i] = rsqrtf((float)g_cnt[i] + fill);
}

// grid-wide offsets: per-block shared scan + atomic block base.
// Offsets are order-nondeterministic across blocks but always form a valid
// disjoint contiguous CSR partition; output values are unaffected.
__global__ void offsets_kernel(int n) {
    __shared__ int s[1024];
    __shared__ int base;
    int t = threadIdx.x;
    int i = blockIdx.x * 1024 + t;
    int v = (i < n) ? g_cnt[i] : 0;
    s[t] = v;
    __syncthreads();
    for (int d = 1; d < 1024; d <<= 1) {
        int u = (t >= d) ? s[t - d] : 0;
        __syncthreads();
        s[t] += u;
        __syncthreads();
    }
    if (t == 1023) base = atomicAdd(&g_total, s[1023]);
    __syncthreads();
    if (i < n) g_off[i] = base + s[t] - v;
}

__global__ void fill_kernel(const int* __restrict__ rows,
                            const int* __restrict__ cols, int E) {
    int e = blockIdx.x * blockDim.x + threadIdx.x;
    if (e < E) {
        int r = rows[e];
        int c = cols[e];
        int p = g_off[r] + atomicAdd(&g_cur[r], 1);
        g_ccol[p]  = c;
        g_cnorm[p] = g_dinv[r] * g_dinv[c];
    }
}

// ---------------- packed f32x2 helpers -------------------------------------
__device__ __forceinline__ unsigned long long pack2(float lo, float hi) {
    unsigned long long r;
    asm("mov.b64 %0, {%1, %2};" : "=l"(r) : "f"(lo), "f"(hi));
    return r;
}
__device__ __forceinline__ void ffma2(unsigned long long& d,
                                      unsigned long long a,
                                      unsigned long long b) {
    asm("fma.rn.f32x2 %0, %1, %2, %0;" : "+l"(d) : "l"(a), "l"(b));
}

// ---------------- fp32x2 tiled GEMM: C[M x 128] = A[M x K] @ B[K x 128] ----
// 64-row blocks, 256 threads. Thread computes 8 rows x 4 cols, rows packed
// in pairs as f32x2 -> 16 FFMA2 per k instead of 32 FFMA.
#define KC 16
__global__ void gemm128_kernel(const float* __restrict__ A,
                               const float* __restrict__ B,
                               float* __restrict__ C, int M, int K) {
    __shared__ float As[KC][64];    // [k][m] (m contiguous -> packed row pairs)
    __shared__ float Bs[KC][128];   // [k][n]
    int tid = threadIdx.x;
    int m0  = blockIdx.x * 64;
    int ty  = tid >> 5;             // 0..7 row-group (warp-uniform)
    int tx  = tid & 31;             // col-group (4 cols each)

    unsigned long long acc[4][4];   // [row-pair][col] packed (r0,r1)
#pragma unroll
    for (int p = 0; p < 4; p++)
#pragma unroll
        for (int j = 0; j < 4; j++) acc[p][j] = 0ull;

    for (int k0 = 0; k0 < K; k0 += KC) {
        // A tile: 64 x 16, each thread one float4 along k
        {
            int r  = tid >> 2;
            int kq = (tid & 3) * 4;
            int gm = m0 + r;
            float4 a = make_float4(0.f, 0.f, 0.f, 0.f);
            if (gm < M) a = *(const float4*)&A[(size_t)gm * K + k0 + kq];
            As[kq + 0][r] = a.x;
            As[kq + 1][r] = a.y;
            As[kq + 2][r] = a.z;
            As[kq + 3][r] = a.w;
        }
        // B tile: 16 x 128 -> 2 float4 per thread
#pragma unroll
        for (int i = 0; i < 2; i++) {
            int idx = tid + i * 256;
            int kk  = idx >> 5;
            int c4  = idx & 31;
            *(float4*)&Bs[kk][c4 * 4] =
                *(const float4*)&B[(size_t)(k0 + kk) * 128 + c4 * 4];
        }
        __syncthreads();
#pragma unroll
        for (int k = 0; k < KC; k++) {
            // 8 consecutive rows = 4 packed pairs (warp-uniform broadcast LDS)
            ulonglong2 a01 = *(const ulonglong2*)&As[k][ty * 8];
            ulonglong2 a23 = *(const ulonglong2*)&As[k][ty * 8 + 4];
            float4 b = *(const float4*)&Bs[k][tx * 4];
            unsigned long long b0 = pack2(b.x, b.x);
            unsigned long long b1 = pack2(b.y, b.y);
            unsigned long long b2 = pack2(b.z, b.z);
            unsigned long long b3 = pack2(b.w, b.w);
            ffma2(acc[0][0], a01.x, b0); ffma2(acc[0][1], a01.x, b1);
            ffma2(acc[0][2], a01.x, b2); ffma2(acc[0][3], a01.x, b3);
            ffma2(acc[1][0], a01.y, b0); ffma2(acc[1][1], a01.y, b1);
            ffma2(acc[1][2], a01.y, b2); ffma2(acc[1][3], a01.y, b3);
            ffma2(acc[2][0], a23.x, b0); ffma2(acc[2][1], a23.x, b1);
            ffma2(acc[2][2], a23.x, b2); ffma2(acc[2][3], a23.x, b3);
            ffma2(acc[3][0], a23.y, b0); ffma2(acc[3][1], a23.y, b1);
            ffma2(acc[3][2], a23.y, b2); ffma2(acc[3][3], a23.y, b3);
        }
        __syncthreads();
    }
    // store: row pair p holds rows (ty*8 + 2p, ty*8 + 2p + 1)
#pragma unroll
    for (int p = 0; p < 4; p++) {
        int gm = m0 + ty * 8 + 2 * p;
#pragma unroll
        for (int half = 0; half < 2; half++) {
            if (gm + half < M) {
                float2 c0 = *(((const float2*)&acc[p][0]) + half ? (const float2*)0 : (const float2*)0);
                // unpack: acc[p][j] = (row_lo, row_hi) packed floats
                float v0, v1, v2, v3;
                {
                    float lo, hi;
                    asm("mov.b64 {%0, %1}, %2;" : "=f"(lo), "=f"(hi) : "l"(acc[p][0]));
                    v0 = half ? hi : lo;
                    asm("mov.b64 {%0, %1}, %2;" : "=f"(lo), "=f"(hi) : "l"(acc[p][1]));
                    v1 = half ? hi : lo;
                    asm("mov.b64 {%0, %1}, %2;" : "=f"(lo), "=f"(hi) : "l"(acc[p][2]));
                    v2 = half ? hi : lo;
                    asm("mov.b64 {%0, %1}, %2;" : "=f"(lo), "=f"(hi) : "l"(acc[p][3]));
                    v3 = half ? hi : lo;
                }
                float4 o = make_float4(v0, v1, v2, v3);
                *(float4*)&C[(size_t)(gm + half) * 128 + tx * 4] = o;
            }
        }
    }
}

// ---------------- aggregation: out[r] = sum_e norm_e * h[col_e] + self ----
template <bool RELU>
__global__ void agg_kernel(const float* __restrict__ h,
                           float* __restrict__ out, int n, float fill) {
    int warp = (blockIdx.x * blockDim.x + threadIdx.x) >> 5;
    int lane = threadIdx.x & 31;
    if (warp >= n) return;
    const float4* hv = (const float4*)h;

    float di = g_dinv[warp];
    float ws = fill * di * di;
    float4 v = hv[(size_t)warp * 32 + lane];
    float4 acc = make_float4(ws * v.x, ws * v.y, ws * v.z, ws * v.w);

    int s = g_off[warp];
    int c = g_cnt[warp];
    int j = 0;
    for (; j + 4 <= c; j += 4) {
        int   c0 = __ldg(&g_ccol[s + j + 0]);
        int   c1 = __ldg(&g_ccol[s + j + 1]);
        int   c2 = __ldg(&g_ccol[s + j + 2]);
        int   c3 = __ldg(&g_ccol[s + j + 3]);
        float w0 = __ldg(&g_cnorm[s + j + 0]);
        float w1 = __ldg(&g_cnorm[s + j + 1]);
        float w2 = __ldg(&g_cnorm[s + j + 2]);
        float w3 = __ldg(&g_cnorm[s + j + 3]);
        float4 u0 = hv[(size_t)c0 * 32 + lane];
        float4 u1 = hv[(size_t)c1 * 32 + lane];
        float4 u2 = hv[(size_t)c2 * 32 + lane];
        float4 u3 = hv[(size_t)c3 * 32 + lane];
        acc.x += w0 * u0.x; acc.y += w0 * u0.y; acc.z += w0 * u0.z; acc.w += w0 * u0.w;
        acc.x += w1 * u1.x; acc.y += w1 * u1.y; acc.z += w1 * u1.z; acc.w += w1 * u1.w;
        acc.x += w2 * u2.x; acc.y += w2 * u2.y; acc.z += w2 * u2.z; acc.w += w2 * u2.w;
        acc.x += w3 * u3.x; acc.y += w3 * u3.y; acc.z += w3 * u3.z; acc.w += w3 * u3.w;
    }
    for (; j < c; j++) {
        int   col = __ldg(&g_ccol[s + j]);
        float w   = __ldg(&g_cnorm[s + j]);
        float4 u  = hv[(size_t)col * 32 + lane];
        acc.x += w * u.x; acc.y += w * u.y; acc.z += w * u.z; acc.w += w * u.w;
    }
    if (RELU) {
        acc.x = fmaxf(acc.x, 0.f);
        acc.y = fmaxf(acc.y, 0.f);
        acc.z = fmaxf(acc.z, 0.f);
        acc.w = fmaxf(acc.w, 0.f);
    }
    *(float4*)&out[(size_t)warp * 128 + lane * 4] = acc;
}

// ---------------- classifier: out[n,c] = h[n,:] . W3[c,:] + b3[c] ----------
__global__ void cls_kernel(const float* __restrict__ h,
                           const float* __restrict__ W3,
                           const float* __restrict__ b3,
                           float* __restrict__ out, int n) {
    __shared__ float sW[N_CLS * HID];
    __shared__ float sb[N_CLS];
    for (int i = threadIdx.x; i < N_CLS * HID; i += blockDim.x) sW[i] = W3[i];
    if (threadIdx.x < N_CLS) sb[threadIdx.x] = b3[threadIdx.x];
    __syncthreads();

    int warp = (blockIdx.x * blockDim.x + threadIdx.x) >> 5;
    int lane = threadIdx.x & 31;
    if (warp >= n) return;

    float4 v = *(const float4*)&h[(size_t)warp * 128 + lane * 4];
#pragma unroll
    for (int c = 0; c < N_CLS; c++) {
        float4 w = *(const float4*)&sW[c * 128 + lane * 4];
        float  p = v.x * w.x + v.y * w.y + v.z * w.z + v.w * w.w;
        p += __shfl_xor_sync(0xffffffffu, p, 16);
        p += __shfl_xor_sync(0xffffffffu, p, 8);
        p += __shfl_xor_sync(0xffffffffu, p, 4);
        p += __shfl_xor_sync(0xffffffffu, p, 2);
        p += __shfl_xor_sync(0xffffffffu, p, 1);
        if (lane == 0) out[(size_t)warp * N_CLS + c] = p + sb[c];
    }
}

// ---------------- launch ---------------------------------------------------
extern "C" void kernel_launch(void* const* d_in, const int* in_sizes, int n_in,
                              void* d_out, int out_size) {
    const float* x  = (const float*)d_in[0];
    const int*   ei = (const int*)d_in[1];
    const float* W1 = (const float*)d_in[2];
    const float* W2 = (const float*)d_in[3];
    const float* W3 = (const float*)d_in[4];
    const float* b3 = (const float*)d_in[5];
    float* out = (float*)d_out;

    const int E = in_sizes[1] / 2;
    const int N = in_sizes[0] / F_IN;
    const int* rows = ei;
    const int* cols = ei + E;
    const float fill = truncf(log2f((float)E / (float)N));

    float* bufA;  cudaGetSymbolAddress((void**)&bufA, g_bufA);
    float* bufB;  cudaGetSymbolAddress((void**)&bufB, g_bufB);

    const int T = 256;
    // --- CSR build ---
    zero_kernel<<<(N + T - 1) / T, T>>>(N);
    count_kernel<<<(E + T - 1) / T, T>>>(rows, E);
    dinv_kernel<<<(N + T - 1) / T, T>>>(N, fill);
    offsets_kernel<<<(N + 1023) / 1024, 1024>>>(N);
    fill_kernel<<<(E + T - 1) / T, T>>>(rows, cols, E);

    // --- layer 1: X @ W1 -> aggregate -> ReLU ---
    gemm128_kernel<<<(N + 63) / 64, 256>>>(x, W1, bufA, N, F_IN);
    agg_kernel<true><<<(N * 32 + T - 1) / T, T>>>(bufA, bufB, N, fill);

    // --- layer 2: H1 @ W2 -> aggregate ---
    gemm128_kernel<<<(N + 63) / 64, 256>>>(bufB, W2, bufA, N, HID);
    agg_kernel<false><<<(N * 32 + T - 1) / T, T>>>(bufA, bufB, N, fill);

    // --- classifier ---
    cls_kernel<<<(N * 32 + T - 1) / T, T>>>(bufB, W3, b3, out, N);
}

// round 4
// speedup vs baseline: 1.5430x; 1.2961x over previous
#include <cuda_runtime.h>
#include <cuda_bf16.h>
#include <cstdint>
#include <math.h>

#define N_NODES 100000
#define N_EDGES 3200000
#define F_IN    512
#define HID     128
#define N_CLS   16

typedef unsigned short u16;

// ---------------- scratch (static device globals; no allocation) ----------
__device__ int   g_cnt[N_NODES];
__device__ int   g_off[N_NODES];
__device__ int   g_cur[N_NODES];
__device__ float g_dinv[N_NODES];
__device__ int   g_total;
__device__ int   g_ccol[N_EDGES];
__device__ float g_cnorm[N_EDGES];
__device__ float g_bufA[(size_t)N_NODES * HID];
__device__ float g_bufB[(size_t)N_NODES * HID];
// W in bf16 hi/lo, [n][k] layout (transposed: B operand of mma row.col)
__device__ u16 g_w1hi[HID * F_IN];
__device__ u16 g_w1lo[HID * F_IN];
__device__ u16 g_w2hi[HID * HID];
__device__ u16 g_w2lo[HID * HID];

// ---------------- helpers ---------------------------------------------------
__device__ __forceinline__ uint32_t smem_to_u32(const void* p) {
    uint32_t a;
    asm("{ .reg .u64 t; cvta.to.shared.u64 t, %1; cvt.u32.u64 %0, t; }"
        : "=r"(a) : "l"(p));
    return a;
}

#define LDSM4(r0, r1, r2, r3, addr)                                        \
    asm volatile("ldmatrix.sync.aligned.m8n8.x4.shared.b16 {%0,%1,%2,%3}, [%4];" \
                 : "=r"(r0), "=r"(r1), "=r"(r2), "=r"(r3) : "r"(addr))

#define MMA_BF16(d, a, b)                                                  \
    asm volatile("mma.sync.aligned.m16n8k16.row.col.f32.bf16.bf16.f32 "    \
                 "{%0,%1,%2,%3}, {%4,%5,%6,%7}, {%8,%9}, {%0,%1,%2,%3};"   \
                 : "+f"((d)[0]), "+f"((d)[1]), "+f"((d)[2]), "+f"((d)[3])  \
                 : "r"((a)[0]), "r"((a)[1]), "r"((a)[2]), "r"((a)[3]),     \
                   "r"((b)[0]), "r"((b)[1]))

__device__ __forceinline__ void split2(float x, float y,
                                       unsigned& hi, unsigned& lo) {
    __nv_bfloat162 h = __floats2bfloat162_rn(x, y);
    float rx = x - __bfloat162float(h.x);
    float ry = y - __bfloat162float(h.y);
    __nv_bfloat162 l = __floats2bfloat162_rn(rx, ry);
    hi = *reinterpret_cast<unsigned*>(&h);
    lo = *reinterpret_cast<unsigned*>(&l);
}

// ---------------- CSR construction ----------------------------------------
__global__ void zero_kernel(int n) {
    int i = blockIdx.x * blockDim.x + threadIdx.x;
    if (i < n) { g_cnt[i] = 0; g_cur[i] = 0; }
    if (i == 0) g_total = 0;
}

__global__ void count_kernel(const int* __restrict__ rows, int E) {
    int e = blockIdx.x * blockDim.x + threadIdx.x;
    if (e < E) atomicAdd(&g_cnt[rows[e]], 1);
}

__global__ void dinv_kernel(int n, float fill) {
    int i = blockIdx.x * blockDim.x + threadIdx.x;
    if (i < n) g_dinv[i] = rsqrtf((float)g_cnt[i] + fill);
}

__global__ void offsets_kernel(int n) {
    __shared__ int s[1024];
    __shared__ int base;
    int t = threadIdx.x;
    int i = blockIdx.x * 1024 + t;
    int v = (i < n) ? g_cnt[i] : 0;
    s[t] = v;
    __syncthreads();
    for (int d = 1; d < 1024; d <<= 1) {
        int u = (t >= d) ? s[t - d] : 0;
        __syncthreads();
        s[t] += u;
        __syncthreads();
    }
    if (t == 1023) base = atomicAdd(&g_total, s[1023]);
    __syncthreads();
    if (i < n) g_off[i] = base + s[t] - v;
}

__global__ void fill_kernel(const int* __restrict__ rows,
                            const int* __restrict__ cols, int E) {
    int e = blockIdx.x * blockDim.x + threadIdx.x;
    if (e < E) {
        int r = rows[e];
        int c = cols[e];
        int p = g_off[r] + atomicAdd(&g_cur[r], 1);
        g_ccol[p]  = c;
        g_cnorm[p] = g_dinv[r] * g_dinv[c];
    }
}

// ---------------- W prep: transpose + bf16 hi/lo split ---------------------
__global__ void wprep_kernel(const float* __restrict__ W1,
                             const float* __restrict__ W2) {
    int i = blockIdx.x * blockDim.x + threadIdx.x;
    if (i < HID * F_IN) {
        int n = i / F_IN, k = i % F_IN;
        float v = W1[k * HID + n];
        __nv_bfloat16 h = __float2bfloat16_rn(v);
        __nv_bfloat16 l = __float2bfloat16_rn(v - __bfloat162float(h));
        g_w1hi[i] = *reinterpret_cast<u16*>(&h);
        g_w1lo[i] = *reinterpret_cast<u16*>(&l);
    }
    int j = i - HID * F_IN;
    if (j >= 0 && j < HID * HID) {
        int n = j / HID, k = j % HID;
        float v = W2[k * HID + n];
        __nv_bfloat16 h = __float2bfloat16_rn(v);
        __nv_bfloat16 l = __float2bfloat16_rn(v - __bfloat162float(h));
        g_w2hi[j] = *reinterpret_cast<u16*>(&h);
        g_w2lo[j] = *reinterpret_cast<u16*>(&l);
    }
}

// ---------------- HMMA bf16-split GEMM: C[M x 128] = A[M x K] @ B^T --------
// Block tile 128x128, 8 warps (warp tile 32x64), K chunks of 32.
// A fp32 gmem -> bf16 hi/lo in smem (on-the-fly). B pre-split [n][k] in gmem.
#define BM  128
#define BN  128
#define KCC 32
#define PADK 40   // padded k-extent in bf16 elems (80 bytes/row: conflict-free ldmatrix)

// ldmatrix.x4 lane address: rows row0..row0+15 at kb, then same rows at kb+8
__device__ __forceinline__ uint32_t qaddr(uint32_t base, int row0, int kb) {
    int L = threadIdx.x & 31;
    int r = row0 + (L & 15);
    int k = kb + (L >> 4) * 8;
    return base + (uint32_t)(r * (PADK * 2) + k * 2);
}

__global__ void __launch_bounds__(256)
mmagemm_kernel(const float* __restrict__ A,
               const u16* __restrict__ Bhi,
               const u16* __restrict__ Blo,
               float* __restrict__ C, int M, int K) {
    __shared__ __align__(16) u16 As_hi[BM][PADK];
    __shared__ __align__(16) u16 As_lo[BM][PADK];
    __shared__ __align__(16) u16 Bs_hi[BN][PADK];
    __shared__ __align__(16) u16 Bs_lo[BN][PADK];

    int tid  = threadIdx.x;
    int wid  = tid >> 5;
    int lane = tid & 31;
    int wr   = wid & 3;    // warp row: 32 rows
    int wc   = wid >> 2;   // warp col: 64 cols
    int m0   = blockIdx.x * BM;

    float acc[2][8][4];
#pragma unroll
    for (int mt = 0; mt < 2; mt++)
#pragma unroll
        for (int nt = 0; nt < 8; nt++)
#pragma unroll
            for (int e = 0; e < 4; e++) acc[mt][nt][e] = 0.f;

    uint32_t ah_base = smem_to_u32(As_hi);
    uint32_t al_base = smem_to_u32(As_lo);
    uint32_t bh_base = smem_to_u32(Bs_hi);
    uint32_t bl_base = smem_to_u32(Bs_lo);

    for (int k0 = 0; k0 < K; k0 += KCC) {
        // A: 128 x 32 fp32 -> hi/lo bf16 (1024 float4, 4 per thread)
#pragma unroll
        for (int i = 0; i < 4; i++) {
            int idx = tid + i * 256;
            int r = idx >> 3;
            int q = idx & 7;
            float4 a = make_float4(0.f, 0.f, 0.f, 0.f);
            if (m0 + r < M)
                a = *(const float4*)&A[(size_t)(m0 + r) * K + k0 + q * 4];
            unsigned h0, l0, h1, l1;
            split2(a.x, a.y, h0, l0);
            split2(a.z, a.w, h1, l1);
            *(uint2*)&As_hi[r][q * 4] = make_uint2(h0, h1);
            *(uint2*)&As_lo[r][q * 4] = make_uint2(l0, l1);
        }
        // B: 128 x 32 bf16 hi/lo (512 uint4 per buffer, 2 per thread)
#pragma unroll
        for (int i = 0; i < 2; i++) {
            int idx = tid + i * 256;
            int r = idx >> 2;
            int q = idx & 3;
            *(uint4*)&Bs_hi[r][q * 8] = *(const uint4*)&Bhi[(size_t)r * K + k0 + q * 8];
            *(uint4*)&Bs_lo[r][q * 8] = *(const uint4*)&Blo[(size_t)r * K + k0 + q * 8];
        }
        __syncthreads();

#pragma unroll
        for (int ks = 0; ks < KCC; ks += 16) {
            uint32_t ah[2][4], al[2][4];
#pragma unroll
            for (int mt = 0; mt < 2; mt++) {
                LDSM4(ah[mt][0], ah[mt][1], ah[mt][2], ah[mt][3],
                      qaddr(ah_base, wr * 32 + mt * 16, ks));
                LDSM4(al[mt][0], al[mt][1], al[mt][2], al[mt][3],
                      qaddr(al_base, wr * 32 + mt * 16, ks));
            }
            uint32_t bh[8][2], bl[8][2];
#pragma unroll
            for (int g = 0; g < 4; g++) {
                uint32_t r0, r1, r2, r3;
                LDSM4(r0, r1, r2, r3, qaddr(bh_base, wc * 64 + g * 16, ks));
                bh[g * 2][0] = r0; bh[g * 2][1] = r2;
                bh[g * 2 + 1][0] = r1; bh[g * 2 + 1][1] = r3;
                LDSM4(r0, r1, r2, r3, qaddr(bl_base, wc * 64 + g * 16, ks));
                bl[g * 2][0] = r0; bl[g * 2][1] = r2;
                bl[g * 2 + 1][0] = r1; bl[g * 2 + 1][1] = r3;
            }
#pragma unroll
            for (int mt = 0; mt < 2; mt++)
#pragma unroll
                for (int nt = 0; nt < 8; nt++) {
                    MMA_BF16(acc[mt][nt], ah[mt], bh[nt]);
                    MMA_BF16(acc[mt][nt], ah[mt], bl[nt]);
                    MMA_BF16(acc[mt][nt], al[mt], bh[nt]);
                }
        }
        __syncthreads();
    }

    // epilogue: D frag -> C
    int rbase = m0 + wr * 32 + (lane >> 2);
    int cbase = wc * 64 + (lane & 3) * 2;
#pragma unroll
    for (int mt = 0; mt < 2; mt++)
#pragma unroll
        for (int nt = 0; nt < 8; nt++) {
            int r = rbase + mt * 16;
            int c = cbase + nt * 8;
            if (r < M)
                *(float2*)&C[(size_t)r * 128 + c] =
                    make_float2(acc[mt][nt][0], acc[mt][nt][1]);
            if (r + 8 < M)
                *(float2*)&C[(size_t)(r + 8) * 128 + c] =
                    make_float2(acc[mt][nt][2], acc[mt][nt][3]);
        }
}

// ---------------- aggregation: out[r] = sum_e norm_e * h[col_e] + self ----
template <bool RELU>
__global__ void agg_kernel(const float* __restrict__ h,
                           float* __restrict__ out, int n, float fill) {
    int warp = (blockIdx.x * blockDim.x + threadIdx.x) >> 5;
    int lane = threadIdx.x & 31;
    if (warp >= n) return;
    const float4* hv = (const float4*)h;

    float di = g_dinv[warp];
    float ws = fill * di * di;
    float4 v = hv[(size_t)warp * 32 + lane];
    float4 acc = make_float4(ws * v.x, ws * v.y, ws * v.z, ws * v.w);

    int s = g_off[warp];
    int c = g_cnt[warp];
    int j = 0;
    for (; j + 4 <= c; j += 4) {
        int   c0 = __ldg(&g_ccol[s + j + 0]);
        int   c1 = __ldg(&g_ccol[s + j + 1]);
        int   c2 = __ldg(&g_ccol[s + j + 2]);
        int   c3 = __ldg(&g_ccol[s + j + 3]);
        float w0 = __ldg(&g_cnorm[s + j + 0]);
        float w1 = __ldg(&g_cnorm[s + j + 1]);
        float w2 = __ldg(&g_cnorm[s + j + 2]);
        float w3 = __ldg(&g_cnorm[s + j + 3]);
        float4 u0 = hv[(size_t)c0 * 32 + lane];
        float4 u1 = hv[(size_t)c1 * 32 + lane];
        float4 u2 = hv[(size_t)c2 * 32 + lane];
        float4 u3 = hv[(size_t)c3 * 32 + lane];
        acc.x += w0 * u0.x; acc.y += w0 * u0.y; acc.z += w0 * u0.z; acc.w += w0 * u0.w;
        acc.x += w1 * u1.x; acc.y += w1 * u1.y; acc.z += w1 * u1.z; acc.w += w1 * u1.w;
        acc.x += w2 * u2.x; acc.y += w2 * u2.y; acc.z += w2 * u2.z; acc.w += w2 * u2.w;
        acc.x += w3 * u3.x; acc.y += w3 * u3.y; acc.z += w3 * u3.z; acc.w += w3 * u3.w;
    }
    for (; j < c; j++) {
        int   col = __ldg(&g_ccol[s + j]);
        float w   = __ldg(&g_cnorm[s + j]);
        float4 u  = hv[(size_t)col * 32 + lane];
        acc.x += w * u.x; acc.y += w * u.y; acc.z += w * u.z; acc.w += w * u.w;
    }
    if (RELU) {
        acc.x = fmaxf(acc.x, 0.f);
        acc.y = fmaxf(acc.y, 0.f);
        acc.z = fmaxf(acc.z, 0.f);
        acc.w = fmaxf(acc.w, 0.f);
    }
    *(float4*)&out[(size_t)warp * 128 + lane * 4] = acc;
}

// ---------------- classifier -----------------------------------------------
__global__ void cls_kernel(const float* __restrict__ h,
                           const float* __restrict__ W3,
                           const float* __restrict__ b3,
                           float* __restrict__ out, int n) {
    __shared__ float sW[N_CLS * HID];
    __shared__ float sb[N_CLS];
    for (int i = threadIdx.x; i < N_CLS * HID; i += blockDim.x) sW[i] = W3[i];
    if (threadIdx.x < N_CLS) sb[threadIdx.x] = b3[threadIdx.x];
    __syncthreads();

    int warp = (blockIdx.x * blockDim.x + threadIdx.x) >> 5;
    int lane = threadIdx.x & 31;
    if (warp >= n) return;

    float4 v = *(const float4*)&h[(size_t)warp * 128 + lane * 4];
#pragma unroll
    for (int c = 0; c < N_CLS; c++) {
        float4 w = *(const float4*)&sW[c * 128 + lane * 4];
        float  p = v.x * w.x + v.y * w.y + v.z * w.z + v.w * w.w;
        p += __shfl_xor_sync(0xffffffffu, p, 16);
        p += __shfl_xor_sync(0xffffffffu, p, 8);
        p += __shfl_xor_sync(0xffffffffu, p, 4);
        p += __shfl_xor_sync(0xffffffffu, p, 2);
        p += __shfl_xor_sync(0xffffffffu, p, 1);
        if (lane == 0) out[(size_t)warp * N_CLS + c] = p + sb[c];
    }
}

// ---------------- launch ---------------------------------------------------
extern "C" void kernel_launch(void* const* d_in, const int* in_sizes, int n_in,
                              void* d_out, int out_size) {
    const float* x  = (const float*)d_in[0];
    const int*   ei = (const int*)d_in[1];
    const float* W1 = (const float*)d_in[2];
    const float* W2 = (const float*)d_in[3];
    const float* W3 = (const float*)d_in[4];
    const float* b3 = (const float*)d_in[5];
    float* out = (float*)d_out;

    const int E = in_sizes[1] / 2;
    const int N = in_sizes[0] / F_IN;
    const int* rows = ei;
    const int* cols = ei + E;
    const float fill = truncf(log2f((float)E / (float)N));

    float* bufA;  cudaGetSymbolAddress((void**)&bufA, g_bufA);
    float* bufB;  cudaGetSymbolAddress((void**)&bufB, g_bufB);
    u16 *w1hi, *w1lo, *w2hi, *w2lo;
    cudaGetSymbolAddress((void**)&w1hi, g_w1hi);
    cudaGetSymbolAddress((void**)&w1lo, g_w1lo);
    cudaGetSymbolAddress((void**)&w2hi, g_w2hi);
    cudaGetSymbolAddress((void**)&w2lo, g_w2lo);

    const int T = 256;
    const int WTOT = HID * F_IN + HID * HID;

    // order chosen so the profiled launch is gemm layer 1
    wprep_kernel<<<(WTOT + T - 1) / T, T>>>(W1, W2);                               // 0
    zero_kernel<<<(N + T - 1) / T, T>>>(N);                                        // 1
    count_kernel<<<(E + T - 1) / T, T>>>(rows, E);                                 // 2
    mmagemm_kernel<<<(N + BM - 1) / BM, 256>>>(x, w1hi, w1lo, bufA, N, F_IN);      // 3
    dinv_kernel<<<(N + T - 1) / T, T>>>(N, fill);                                  // 4
    offsets_kernel<<<(N + 1023) / 1024, 1024>>>(N);                                // 5
    fill_kernel<<<(E + T - 1) / T, T>>>(rows, cols, E);                            // 6
    agg_kernel<true><<<(N * 32 + T - 1) / T, T>>>(bufA, bufB, N, fill);            // 7
    mmagemm_kernel<<<(N + BM - 1) / BM, 256>>>(bufB, w2hi, w2lo, bufA, N, HID);    // 8
    agg_kernel<false><<<(N * 32 + T - 1) / T, T>>>(bufA, bufB, N, fill);           // 9
    cls_kernel<<<(N * 32 + T - 1) / T, T>>>(bufB, W3, b3, out, N);                 // 10
}